// round 7
// baseline (speedup 1.0000x reference)
#include <cuda_runtime.h>
#include <cuda_bf16.h>
#include <cstdint>

// DotAttentionEluX — math collapses:
//   attn[i,j] = ks_j / sum_j ks_j  (query cancels in row normalization)
//   out[b,h,i,:] = (sum_j ks_j * v_j) / (sum_j ks_j)   -- same for every row i
// with ks_j = sum_d (elu(k[b,h,j,d]) + 1).
//
// R4-R6: the write kernel sat at ~7us regardless of mechanism (STG vs bulk,
// occ 13-62%) with all pipes <25% -> per-kernel floor, not a pipe limit.
// R7: single persistent kernel, device-wide barrier (512 co-resident CTAs),
// phase 2 stages 8KB once and bulk-copies it 4x to the CTA's 128-row range.

static constexpr int B_ = 4, H_ = 8, L_ = 2048, D_ = 64;
static constexpr int BH = B_ * H_;                  // 32
static constexpr int NSPLIT = 16;
static constexpr int ROWS_PER_SPLIT = L_ / NSPLIT;  // 128
static constexpr int WARPS = 8;
static constexpr int NCTA = BH * NSPLIT;            // 512

__device__ float g_num[BH * NSPLIT * D_];
__device__ float g_den[BH * NSPLIT];
__device__ int   g_arrive;   // zero-initialized; self-resets each launch
__device__ int   g_done;

__device__ __forceinline__ float elu1(float x) {
    return x > 0.0f ? x + 1.0f : __expf(x);
}

static constexpr int STAGE_ROWS = 32;                       // rows staged in smem
static constexpr int STAGE_BYTES = STAGE_ROWS * D_ * 4;     // 8192

__global__ __launch_bounds__(256) void fused_kernel(
    const float* __restrict__ K, const float* __restrict__ V,
    float* __restrict__ out)
{
    const int blk   = blockIdx.x;       // 0..511
    const int bh    = blk / NSPLIT;
    const int split = blk % NSPLIT;
    const int t     = threadIdx.x;
    const int warp  = t >> 5;
    const int lane  = t & 31;
    const int half  = lane >> 4;        // which row of the pair
    const int q     = lane & 15;        // float4 slot within the row

    // ---------------- Phase 1: accumulate this split's partials ----------
    {
        const size_t base = ((size_t)bh * L_ + split * ROWS_PER_SPLIT
                             + (size_t)warp * 2 + half) * D_ + (size_t)q * 4;
        const float4* __restrict__ Kp = reinterpret_cast<const float4*>(K + base);
        const float4* __restrict__ Vp = reinterpret_cast<const float4*>(V + base);
        constexpr int STRIDE4 = WARPS * 2 * D_ / 4;
        constexpr int NPAIR   = ROWS_PER_SPLIT / (WARPS * 2);   // 8

        float n0 = 0.f, n1 = 0.f, n2 = 0.f, n3 = 0.f, den = 0.f;
        #pragma unroll
        for (int r = 0; r < NPAIR; r++) {
            float4 kk = Kp[(size_t)r * STRIDE4];
            float4 vv = Vp[(size_t)r * STRIDE4];
            float ks = elu1(kk.x) + elu1(kk.y) + elu1(kk.z) + elu1(kk.w);
            #pragma unroll
            for (int o = 8; o; o >>= 1)
                ks += __shfl_xor_sync(0xffffffffu, ks, o);
            n0 += ks * vv.x;  n1 += ks * vv.y;
            n2 += ks * vv.z;  n3 += ks * vv.w;
            if (q == 0) den += ks;
        }

        __shared__ float4 s_num[WARPS * 2][D_ / 4];
        __shared__ float  s_den[WARPS * 2];
        const int wh = warp * 2 + half;
        s_num[wh][q] = make_float4(n0, n1, n2, n3);
        if (q == 0) s_den[wh] = den;
        __syncthreads();

        if (t < D_) {
            const float* sn = reinterpret_cast<const float*>(s_num);
            float s = 0.0f;
            #pragma unroll
            for (int w = 0; w < WARPS * 2; w++) s += sn[w * D_ + t];
            g_num[(bh * NSPLIT + split) * D_ + t] = s;
        }
        if (t == D_) {
            float s = 0.0f;
            #pragma unroll
            for (int w = 0; w < WARPS * 2; w++) s += s_den[w];
            g_den[bh * NSPLIT + split] = s;
        }
    }

    // ---------------- Device-wide barrier (all 512 CTAs co-resident) -----
    __threadfence();          // release: partials visible at L2 before arrive
    __syncthreads();
    if (t == 0) {
        atomicAdd(&g_arrive, 1);
        volatile int* p = &g_arrive;
        while (*p < NCTA) { __nanosleep(64); }
        __threadfence();      // acquire
    }
    __syncthreads();

    // ---------------- Phase 2: finish reduction, stage, bulk-write -------
    __shared__ alignas(128) float4 s_buf[STAGE_ROWS * (D_ / 4)]; // 8 KB
    __shared__ float4 s_w4[D_ / 4];

    if (t < D_) {
        const float* __restrict__ pn = g_num + bh * NSPLIT * D_ + t;
        float num = 0.0f, den = 0.0f;
        #pragma unroll
        for (int sp = 0; sp < NSPLIT; sp++) {
            num += __ldcg(pn + sp * D_);          // L2 reads (bypass L1)
            den += __ldcg(&g_den[bh * NSPLIT + sp]);
        }
        reinterpret_cast<float*>(s_w4)[t] = num / den;
    }
    __syncthreads();

    // Replicate the 256B row into 32 staged rows (2 conflict-free STS.128).
    {
        const float4 v = s_w4[t & 15];
        const int r0 = t >> 4;                    // 0..15
        #pragma unroll
        for (int i = 0; i < STAGE_ROWS / 16; i++) // 2 iters
            s_buf[(r0 + 16 * i) * (D_ / 4) + (t & 15)] = v;
    }
    __syncthreads();

    // 4 bulk copies of the same 8KB buffer cover this CTA's 128 rows.
    if (t == 0) {
        asm volatile("fence.proxy.async.shared::cta;" ::: "memory");
        uint32_t saddr = (uint32_t)__cvta_generic_to_shared(s_buf);
        #pragma unroll
        for (int i = 0; i < ROWS_PER_SPLIT / STAGE_ROWS; i++) {   // 4
            const float* gdst = out + ((size_t)bh * L_
                + (size_t)split * ROWS_PER_SPLIT + (size_t)i * STAGE_ROWS) * D_;
            asm volatile(
                "cp.async.bulk.global.shared::cta.bulk_group [%0], [%1], %2;"
                :: "l"(gdst), "r"(saddr), "r"((int)STAGE_BYTES) : "memory");
        }
        asm volatile("cp.async.bulk.commit_group;" ::: "memory");
        asm volatile("cp.async.bulk.wait_group.read 0;" ::: "memory");

        // Self-reset the barrier counters for the next (graph) launch.
        int d = atomicAdd(&g_done, 1);
        if (d == NCTA - 1) { g_arrive = 0; g_done = 0; }
    }
}

extern "C" void kernel_launch(void* const* d_in, const int* in_sizes, int n_in,
                              void* d_out, int out_size)
{
    // metadata order: query, key, value. Query is mathematically irrelevant.
    const float* K = (const float*)d_in[1];
    const float* V = (const float*)d_in[2];
    float* out = (float*)d_out;

    fused_kernel<<<NCTA, 256>>>(K, V, out);
}